// round 10
// baseline (speedup 1.0000x reference)
#include <cuda_runtime.h>
#include <cstdint>

#define N_ROWS 32768
#define DIM    256
#define NE     8192
#define NW     (DIM / 2)      // 128 packed words per vector

#define TM     128
#define TN     64
#define CH     (NE / TN)      // 128 chunks

#define NCAND  32
#define MARGIN 4.0f

#define INDOFF  (N_ROWS * DIM)         // 2097152
#define LOSSOFF (INDOFF + N_ROWS)      // 2129920

// smem layout (bytes)
#define OFF_A    0                      // 128 w x 128 rows x 4B = 65536
#define OFF_B0   65536                  // 128 w x 64 cols x 4B  = 32768
#define OFF_B1   98304                  // 32768
#define OFF_ADJ  131072                 // 8192 floats = 32768
#define SMEM_BYTES 163840

// Scratch (device globals: allocation-free per harness rules)
__device__ float    g_embedT[(size_t)NE * DIM];  // [8192][256] fp32 codebook rows
__device__ float    g_norms[NE];                 // ||e_j||^2 exact fp32
__device__ unsigned g_pa[(size_t)N_ROWS * NW];   // packed input  [row][w]
__device__ unsigned g_pb[(size_t)NW * NE];       // packed (swapped) codebook [w][j]
__device__ float    g_adjn[NE];                  // ||e||^2 - csc*(128*Se + 2^22)
__device__ unsigned g_maxX, g_maxE;              // float-bits of max|.| -> scales
__device__ float    g_cscale;                    // -2/(sx*se)
__device__ int      g_cand[(size_t)N_ROWS * NCAND];
__device__ int      g_flag[N_ROWS];
__device__ int      g_idx[N_ROWS];
__device__ float    g_partial[N_ROWS / 64];      // 512 loss partials

// ---------------------------------------------------------------------------
// helpers (base-target PTX only)
// ---------------------------------------------------------------------------
__device__ __forceinline__ uint32_t smem_u32(const void* p) {
    uint32_t a;
    asm("{ .reg .u64 t; cvta.to.shared.u64 t, %1; cvt.u32.u64 %0, t; }"
        : "=r"(a) : "l"(p));
    return a;
}
__device__ __forceinline__ void cpasync16(uint32_t dst, const void* src) {
    asm volatile("cp.async.cg.shared.global [%0], [%1], 16;"
                 :: "r"(dst), "l"(src) : "memory");
}
#define CP_COMMIT() asm volatile("cp.async.commit_group;" ::: "memory")
#define CP_WAIT1()  asm volatile("cp.async.wait_group 1;" ::: "memory")
#define CP_WAIT0()  asm volatile("cp.async.wait_group 0;" ::: "memory")

// biased 8-bit quantize: q in [1,255]
__device__ __forceinline__ unsigned q8(float v, float s) {
    return (unsigned)(__float2int_rn(v * s) + 128);
}

// ---------------------------------------------------------------------------
// Prep: transpose embed [256][8192] -> embedT [8192][256]
// ---------------------------------------------------------------------------
__global__ void vq_transpose(const float* __restrict__ embed) {
    __shared__ float tile[32][33];
    int jB = blockIdx.x * 32, dB = blockIdx.y * 32;
    int tx = threadIdx.x, ty = threadIdx.y;
    #pragma unroll
    for (int r = ty; r < 32; r += 8)
        tile[r][tx] = embed[(size_t)(dB + r) * NE + jB + tx];
    __syncthreads();
    #pragma unroll
    for (int r = ty; r < 32; r += 8)
        g_embedT[(size_t)(jB + r) * DIM + dB + tx] = tile[tx][r];
}

// Prep: norms (identical op order to R1 kernel that measured rel_err 0.0)
__global__ void vq_norms() {
    int warp = threadIdx.x >> 5, lane = threadIdx.x & 31;
    int j = blockIdx.x * 8 + warp;
    const float4* row = (const float4*)(g_embedT + (size_t)j * DIM);
    float s = 0.f;
    #pragma unroll
    for (int i = lane; i < DIM / 4; i += 32) {
        float4 v = row[i];
        s += v.x * v.x + v.y * v.y + v.z * v.z + v.w * v.w;
    }
    #pragma unroll
    for (int o = 16; o; o >>= 1) s += __shfl_xor_sync(0xFFFFFFFFu, s, o);
    if (lane == 0) g_norms[j] = s;
}

// Prep: scales (deterministic — max is order-independent)
__global__ void vq_zero_scales() { g_maxX = 0u; g_maxE = 0u; }

__global__ void vq_maxabs(const float* __restrict__ p, int which) {
    __shared__ float red[256];
    int i = blockIdx.x * 256 + threadIdx.x;
    float4 v = ((const float4*)p)[i];
    float m = fmaxf(fmaxf(fabsf(v.x), fabsf(v.y)), fmaxf(fabsf(v.z), fabsf(v.w)));
    red[threadIdx.x] = m;
    __syncthreads();
    #pragma unroll
    for (int s = 128; s; s >>= 1) {
        if (threadIdx.x < s) red[threadIdx.x] = fmaxf(red[threadIdx.x], red[threadIdx.x + s]);
        __syncthreads();
    }
    if (threadIdx.x == 0)
        atomicMax(which ? &g_maxE : &g_maxX, __float_as_uint(red[0]));
}

__global__ void vq_scales() {
    float sx = 126.5f / __uint_as_float(g_maxX);
    float se = 126.5f / __uint_as_float(g_maxE);
    g_cscale = -2.f / (sx * se);
    g_maxX = __float_as_uint(sx);   // reuse slots to carry scales
    g_maxE = __float_as_uint(se);
}

// Prep: pack input: word w (dims 2w,2w+1) -> q(2w+1)<<22 | q(2w)
__global__ void vq_pack_x(const float* __restrict__ input) {
    int i = blockIdx.x * 256 + threadIdx.x;     // float4 index; covers 2 words
    float s = __uint_as_float(g_maxX);
    float4 v = ((const float4*)input)[i];
    g_pa[i * 2 + 0] = (q8(v.y, s) << 22) | q8(v.x, s);
    g_pa[i * 2 + 1] = (q8(v.w, s) << 22) | q8(v.z, s);
}
// Prep: pack codebook SWAPPED: g_pb[w][j] = q(e_2w)<<22 | q(e_2w+1)
__global__ void vq_pack_e(const float* __restrict__ embed) {
    int idx = blockIdx.x * 256 + threadIdx.x;   // 128*8192 words
    int w = idx >> 13, j = idx & (NE - 1);
    float s = __uint_as_float(g_maxE);
    float e0 = embed[(size_t)(2 * w) * NE + j];
    float e1 = embed[(size_t)(2 * w + 1) * NE + j];
    g_pb[idx] = (q8(e0, s) << 22) | q8(e1, s);
}

// Prep: adjn[j] = norms[j] - csc*(128*Se_j + 4194304), Se_j = sum of biased q
__global__ void vq_adjn() {
    int warp = threadIdx.x >> 5, lane = threadIdx.x & 31;
    int j = blockIdx.x * 8 + warp;
    float se = __uint_as_float(g_maxE);
    const float4* row = (const float4*)(g_embedT + (size_t)j * DIM);
    int s = 0;
    #pragma unroll
    for (int i = lane; i < DIM / 4; i += 32) {
        float4 v = row[i];
        s += (__float2int_rn(v.x * se) + 128) + (__float2int_rn(v.y * se) + 128)
           + (__float2int_rn(v.z * se) + 128) + (__float2int_rn(v.w * se) + 128);
    }
    #pragma unroll
    for (int o = 16; o; o >>= 1) s += __shfl_xor_sync(0xFFFFFFFFu, s, o);
    if (lane == 0)
        g_adjn[j] = g_norms[j] - g_cscale * (float)(128 * s + 4194304);
}

// ---------------------------------------------------------------------------
// Main: IMAD.WIDE packed-pair GEMM (2 exact int8 MACs/instr) + top-2 + flag
// 256 threads (tx 0..15 -> 4 cols, ty 0..15 -> 8 rows). TM=128, TN=64.
// ---------------------------------------------------------------------------
__global__ void __launch_bounds__(256, 1) vq_main() {
    extern __shared__ char smem[];
    const uint32_t sb = smem_u32(smem);
    unsigned* As = (unsigned*)(smem + OFF_A);

    const int tid = threadIdx.x;
    const int tx = tid & 15, ty = tid >> 4;
    const int lane = tid & 31;
    const int rowBase = blockIdx.x * TM;
    const float csc = g_cscale;

    // ---- stage A transposed: As[w][row] ----
    #pragma unroll
    for (int it = 0; it < 16; it++) {
        int v = it * 256 + tid;               // 4096 uint4 = 128 rows x 32
        int r = v >> 5, wb = (v & 31) * 4;
        uint4 w = *(const uint4*)(g_pa + (size_t)(rowBase + r) * NW + wb);
        As[(wb + 0) * TM + r] = w.x;
        As[(wb + 1) * TM + r] = w.y;
        As[(wb + 2) * TM + r] = w.z;
        As[(wb + 3) * TM + r] = w.w;
    }

    // ---- cp.async: adjn (32KB) + B chunk staging ----
    auto stageB = [&](uint32_t off, int c) {
        const char* base = (const char*)g_pb;
        for (int v = tid; v < 2048; v += 256) {
            int w = v >> 4, g = v & 15;       // 128 w-rows x 16 granules
            cpasync16(sb + off + (uint32_t)w * 256 + g * 16,
                      base + ((size_t)w * NE + (size_t)c * TN) * 4 + g * 16);
        }
    };
    {
        const char* nsrc = (const char*)g_adjn;
        for (int g = tid; g < 2048; g += 256)
            cpasync16(sb + OFF_ADJ + (uint32_t)g * 16, nsrc + (size_t)g * 16);
    }
    stageB(OFF_B0, 0);
    CP_COMMIT();

    // per-row top-2 (8 rows/thread) over this lane's 4 cols x 128 chunks
    float cs0[8], cs1[8];
    int   ci0[8], ci1[8];
    #pragma unroll
    for (int r = 0; r < 8; r++) {
        cs0[r] = __int_as_float(0x7F800000);
        cs1[r] = __int_as_float(0x7F800000);
        ci0[r] = 0; ci1[r] = 0;
    }
#define INS(r, sc, jj) do {                                                    \
    float _s = (sc); int _j = (jj);                                            \
    if (_s < cs0[r]) { cs1[r] = cs0[r]; ci1[r] = ci0[r];                       \
                       cs0[r] = _s;     ci0[r] = _j; }                         \
    else if (_s < cs1[r]) { cs1[r] = _s; ci1[r] = _j; }                        \
} while (0)

    for (int c = 0; c < CH; c++) {
        __syncthreads();                       // everyone done with this buffer
        if (c + 1 < CH) {
            stageB((c + 1) & 1 ? OFF_B1 : OFF_B0, c + 1);
            CP_COMMIT();
            CP_WAIT1();                        // chunk c's group complete
        } else {
            CP_WAIT0();
        }
        __syncthreads();

        const unsigned* Bb = (const unsigned*)(smem + ((c & 1) ? OFF_B1 : OFF_B0));

        unsigned tot[8][4];
        #pragma unroll
        for (int i = 0; i < 8; i++)
            #pragma unroll
            for (int j = 0; j < 4; j++) tot[i][j] = 0u;

        #pragma unroll
        for (int seg = 0; seg < 4; seg++) {
            unsigned long long S[8][4];
            #pragma unroll
            for (int i = 0; i < 8; i++)
                #pragma unroll
                for (int j = 0; j < 4; j++) S[i][j] = 0ull;

            #pragma unroll 4
            for (int w8 = 0; w8 < 32; w8++) {
                const int w = seg * 32 + w8;
                uint4 a0 = *(const uint4*)(As + w * TM + ty * 8);
                uint4 a1 = *(const uint4*)(As + w * TM + ty * 8 + 4);
                uint4 bq = *(const uint4*)(Bb + w * TN + tx * 4);
                unsigned a[8] = {a0.x, a0.y, a0.z, a0.w, a1.x, a1.y, a1.z, a1.w};
                unsigned b[4] = {bq.x, bq.y, bq.z, bq.w};
                #pragma unroll
                for (int i = 0; i < 8; i++)
                    #pragma unroll
                    for (int j = 0; j < 4; j++)
                        S[i][j] += (unsigned long long)a[i] * b[j];
            }
            // middle field = pair-dot sum (exact): bits [22, 44)
            #pragma unroll
            for (int i = 0; i < 8; i++)
                #pragma unroll
                for (int j = 0; j < 4; j++)
                    tot[i][j] += (unsigned)(S[i][j] >> 22) & 0x3FFFFFu;
        }

        // epilogue: s' = adjn[j] + csc*D (row-constant shift dropped)
        const float* adj = (const float*)(smem + OFF_ADJ);
        const int jb = c * TN + tx * 4;
        float4 a4 = *(const float4*)(adj + jb);
        float an[4] = {a4.x, a4.y, a4.z, a4.w};
        #pragma unroll
        for (int j = 0; j < 4; j++) {
            #pragma unroll
            for (int i = 0; i < 8; i++) {
                float s = fmaf(csc, (float)tot[i][j], an[j]);
                INS(i, s, jb + j);
            }
        }
    }
#undef INS

    // ---- per-row flag + candidate write (16 tx lanes per row) ----
    #pragma unroll
    for (int r = 0; r < 8; r++) {
        float b = cs0[r];
        #pragma unroll
        for (int o = 1; o < 16; o <<= 1)
            b = fminf(b, __shfl_xor_sync(0xFFFFFFFFu, b, o));
        bool f = (cs1[r] <= b + MARGIN);
        unsigned bal = __ballot_sync(0xFFFFFFFFu, f);
        unsigned bits = (bal >> (lane & 16)) & 0xFFFFu;
        const int row = rowBase + ty * 8 + r;
        if (tx == 0) g_flag[row] = (bits != 0u);
        g_cand[(size_t)row * NCAND + tx * 2 + 0] = ci0[r];
        g_cand[(size_t)row * NCAND + tx * 2 + 1] = ci1[r];
    }
}

// ---------------------------------------------------------------------------
// Refine: exact fp32 scores for 32 candidates (1/lane); flagged rows: full
// vectorized exact scan. One warp per row; first-index tie-break.
// ---------------------------------------------------------------------------
__global__ void __launch_bounds__(256) vq_refine(const float* __restrict__ input,
                                                 float* __restrict__ out) {
    const int wid = threadIdx.x >> 5, lane = threadIdx.x & 31;
    const int row = blockIdx.x * 8 + wid;
    const float4* xp = (const float4*)(input + (size_t)row * DIM);

    float bs;
    int   bj;

    if (!g_flag[row]) {
        const int j = g_cand[(size_t)row * NCAND + lane];
        const float4* ep = (const float4*)(g_embedT + (size_t)j * DIM);
        float p0 = 0.f, p1 = 0.f, p2 = 0.f, p3 = 0.f;
        #pragma unroll 8
        for (int i = 0; i < 64; i += 4) {
            float4 x0 = xp[i],     e0 = ep[i];
            float4 x1 = xp[i + 1], e1 = ep[i + 1];
            float4 x2 = xp[i + 2], e2 = ep[i + 2];
            float4 x3 = xp[i + 3], e3 = ep[i + 3];
            p0 = fmaf(x0.x, e0.x, p0); p0 = fmaf(x0.y, e0.y, p0);
            p0 = fmaf(x0.z, e0.z, p0); p0 = fmaf(x0.w, e0.w, p0);
            p1 = fmaf(x1.x, e1.x, p1); p1 = fmaf(x1.y, e1.y, p1);
            p1 = fmaf(x1.z, e1.z, p1); p1 = fmaf(x1.w, e1.w, p1);
            p2 = fmaf(x2.x, e2.x, p2); p2 = fmaf(x2.y, e2.y, p2);
            p2 = fmaf(x2.z, e2.z, p2); p2 = fmaf(x2.w, e2.w, p2);
            p3 = fmaf(x3.x, e3.x, p3); p3 = fmaf(x3.y, e3.y, p3);
            p3 = fmaf(x3.z, e3.z, p3); p3 = fmaf(x3.w, e3.w, p3);
        }
        float p = (p0 + p1) + (p2 + p3);
        bs = fmaf(-2.f, p, g_norms[j]);
        bj = j;
    } else {
        bs = __int_as_float(0x7F800000);
        bj = 0x7FFFFFFF;
        for (int j = lane; j < NE; j += 32) {
            const float4* ep = (const float4*)(g_embedT + (size_t)j * DIM);
            float p0 = 0.f, p1 = 0.f, p2 = 0.f, p3 = 0.f;
            #pragma unroll 4
            for (int i = 0; i < 64; i += 4) {
                float4 x0 = xp[i],     e0 = ep[i];
                float4 x1 = xp[i + 1], e1 = ep[i + 1];
                float4 x2 = xp[i + 2], e2 = ep[i + 2];
                float4 x3 = xp[i + 3], e3 = ep[i + 3];
                p0 = fmaf(x0.x, e0.x, p0); p0 = fmaf(x0.y, e0.y, p0);
                p0 = fmaf(x0.z, e0.z, p0); p0 = fmaf(x0.w, e0.w, p0);
                p1 = fmaf(x1.x, e1.x, p1); p1 = fmaf(x1.y, e1.y, p1);
                p1 = fmaf(x1.z, e1.z, p1); p1 = fmaf(x1.w, e1.w, p1);
                p2 = fmaf(x2.x, e2.x, p2); p2 = fmaf(x2.y, e2.y, p2);
                p2 = fmaf(x2.z, e2.z, p2); p2 = fmaf(x2.w, e2.w, p2);
                p3 = fmaf(x3.x, e3.x, p3); p3 = fmaf(x3.y, e3.y, p3);
                p3 = fmaf(x3.z, e3.z, p3); p3 = fmaf(x3.w, e3.w, p3);
            }
            float p = (p0 + p1) + (p2 + p3);
            float s = fmaf(-2.f, p, g_norms[j]);
            if (s < bs || (s == bs && j < bj)) { bs = s; bj = j; }
        }
    }
    // warp argmin, first-index tie-break (dedups repeated candidates too)
    #pragma unroll
    for (int o = 16; o; o >>= 1) {
        float os = __shfl_xor_sync(0xFFFFFFFFu, bs, o);
        int   oj = __shfl_xor_sync(0xFFFFFFFFu, bj, o);
        if (os < bs || (os == bs && oj < bj)) { bs = os; bj = oj; }
    }
    if (lane == 0) {
        g_idx[row] = bj;
        out[INDOFF + row] = (float)bj;
    }
}

// ---------------------------------------------------------------------------
// Output: gather + straight-through + per-block loss partial
// ---------------------------------------------------------------------------
__global__ void __launch_bounds__(256) vq_output(const float* __restrict__ input,
                                                 float* __restrict__ out) {
    __shared__ int sIdx[64];
    __shared__ float red[256];
    const int tid = threadIdx.x;
    const int rowBase = blockIdx.x * 64;
    if (tid < 64) sIdx[tid] = g_idx[rowBase + tid];
    __syncthreads();
    float lsum = 0.f;
    for (int r = 0; r < 64; r++) {
        int j = sIdx[r];
        float q = g_embedT[(size_t)j * DIM + tid];
        float x = input[(size_t)(rowBase + r) * DIM + tid];
        float d = q - x;
        out[(size_t)(rowBase + r) * DIM + tid] = x + d;   // straight-through
        lsum += d * d;
    }
    red[tid] = lsum;
    __syncthreads();
    #pragma unroll
    for (int s = 128; s; s >>= 1) {
        if (tid < s) red[tid] += red[tid + s];
        __syncthreads();
    }
    if (tid == 0) g_partial[blockIdx.x] = red[0];
}

__global__ void vq_loss_final(float* __restrict__ out) {
    __shared__ float red[512];
    red[threadIdx.x] = g_partial[threadIdx.x];
    __syncthreads();
    #pragma unroll
    for (int s = 256; s; s >>= 1) {
        if (threadIdx.x < s) red[threadIdx.x] += red[threadIdx.x + s];
        __syncthreads();
    }
    if (threadIdx.x == 0)
        out[LOSSOFF] = red[0] * (1.0f / (float)(N_ROWS * DIM));
}

// ---------------------------------------------------------------------------
extern "C" void kernel_launch(void* const* d_in, const int* in_sizes, int n_in,
                              void* d_out, int out_size) {
    const float* input = (const float*)d_in[0];   // [8,64,64,256]
    const float* embed = (const float*)d_in[1];   // [256,8192]
    float* out = (float*)d_out;

    cudaFuncSetAttribute(vq_main, cudaFuncAttributeMaxDynamicSharedMemorySize,
                         SMEM_BYTES);

    vq_transpose<<<dim3(NE / 32, DIM / 32), dim3(32, 8)>>>(embed);
    vq_norms<<<NE / 8, 256>>>();
    vq_zero_scales<<<1, 1>>>();
    vq_maxabs<<<(N_ROWS * DIM / 4) / 256, 256>>>(input, 0);
    vq_maxabs<<<(NE * DIM / 4) / 256, 256>>>(embed, 1);
    vq_scales<<<1, 1>>>();
    vq_pack_x<<<(N_ROWS * NW / 2) / 256, 256>>>(input);
    vq_pack_e<<<(NW * NE) / 256, 256>>>(embed);
    vq_adjn<<<NE / 8, 256>>>();
    vq_main<<<N_ROWS / TM, 256, SMEM_BYTES>>>();
    vq_refine<<<N_ROWS / 8, 256>>>(input, out);
    vq_output<<<N_ROWS / 64, 256>>>(input, out);
    vq_loss_final<<<1, 512>>>(out);
}

// round 11
// speedup vs baseline: 1.8340x; 1.8340x over previous
#include <cuda_runtime.h>
#include <cstdint>

#define N_ROWS 32768
#define DIM    256
#define NE     8192
#define TM     64
#define TN     64
#define NHALF  (NE / 2)        // 4096 codes per job
#define CH     (NHALF / TN)    // 64 chunks per job

#define INDOFF  (N_ROWS * DIM)         // 2097152
#define LOSSOFF (INDOFF + N_ROWS)      // 2129920

// smem layout (bytes)
#define OFF_A    0                      // As[k][m] 256x64 fp32 = 65536
#define OFF_B0   65536                  // Bs[k][j] 256x64 fp32 = 65536
#define OFF_B1   131072                 // 65536
#define OFF_BEST 196608                 // 64 x u64 = 512
#define SMEM_BYTES 197120

// Scratch (device globals: allocation-free per harness rules)
__device__ float              g_embedT[(size_t)NE * DIM]; // [8192][256]
__device__ float              g_norms[NE];                // ||e_j||^2
__device__ unsigned long long g_best[N_ROWS];             // packed (key, idx)
__device__ int                g_idx[N_ROWS];
__device__ float              g_partial[N_ROWS / 64];     // 512 loss partials

// ---------------------------------------------------------------------------
// helpers
// ---------------------------------------------------------------------------
__device__ __forceinline__ uint32_t smem_u32(const void* p) {
    uint32_t a;
    asm("{ .reg .u64 t; cvta.to.shared.u64 t, %1; cvt.u32.u64 %0, t; }"
        : "=r"(a) : "l"(p));
    return a;
}
__device__ __forceinline__ void cpasync16(uint32_t dst, const void* src) {
    asm volatile("cp.async.cg.shared.global [%0], [%1], 16;"
                 :: "r"(dst), "l"(src) : "memory");
}
#define CP_COMMIT() asm volatile("cp.async.commit_group;" ::: "memory")
#define CP_WAIT1()  asm volatile("cp.async.wait_group 1;" ::: "memory")
#define CP_WAIT0()  asm volatile("cp.async.wait_group 0;" ::: "memory")

// ---------------------------------------------------------------------------
// Prep: transpose embed [256][8192] -> embedT [8192][256]
// ---------------------------------------------------------------------------
__global__ void vq_transpose(const float* __restrict__ embed) {
    __shared__ float tile[32][33];
    int jB = blockIdx.x * 32, dB = blockIdx.y * 32;
    int tx = threadIdx.x, ty = threadIdx.y;
    #pragma unroll
    for (int r = ty; r < 32; r += 8)
        tile[r][tx] = embed[(size_t)(dB + r) * NE + jB + tx];
    __syncthreads();
    #pragma unroll
    for (int r = ty; r < 32; r += 8)
        g_embedT[(size_t)(jB + r) * DIM + dB + tx] = tile[tx][r];
}

// Prep: norms (identical op order to the rel_err-0.0 R1 kernel)
__global__ void vq_norms() {
    int warp = threadIdx.x >> 5, lane = threadIdx.x & 31;
    int j = blockIdx.x * 8 + warp;
    const float4* row = (const float4*)(g_embedT + (size_t)j * DIM);
    float s = 0.f;
    #pragma unroll
    for (int i = lane; i < DIM / 4; i += 32) {
        float4 v = row[i];
        s += v.x * v.x + v.y * v.y + v.z * v.z + v.w * v.w;
    }
    #pragma unroll
    for (int o = 16; o; o >>= 1) s += __shfl_xor_sync(0xFFFFFFFFu, s, o);
    if (lane == 0) g_norms[j] = s;
}

// Prep: reset global argmin slots every launch (graph replays!)
__global__ void vq_init() {
    g_best[blockIdx.x * 256 + threadIdx.x] = 0xFFFFFFFFFFFFFFFFull;
}

// ---------------------------------------------------------------------------
// Main: fp32 FFMA GEMM (R1 inner loop) over HALF the codebook per CTA.
// grid (512, 2): x = row tile, y = codebook half. cp.async double-buffered B.
// ---------------------------------------------------------------------------
__global__ void __launch_bounds__(256, 1)
vq_main(const float* __restrict__ input, const float* __restrict__ embed) {
    extern __shared__ float smem[];
    const uint32_t sb = smem_u32(smem);
    float* As = smem;                                     // [256][64]
    unsigned long long* bestP = (unsigned long long*)((char*)smem + OFF_BEST);

    const int tid = threadIdx.x;
    const int tx  = tid & 15;            // 4 cols each
    const int ty  = tid >> 4;            // 4 rows each
    const int rowBase = blockIdx.x * TM;
    const int colBase = blockIdx.y * NHALF;

    if (tid < TM) bestP[tid] = 0xFFFFFFFFFFFFFFFFull;

    // ---- stage A once (transposed As[k][m]) ----
    {
        const float4* Ain = (const float4*)(input + (size_t)rowBase * DIM);
        #pragma unroll
        for (int p = 0; p < 16; p++) {
            int f4 = p * 256 + tid;        // 4096 float4s (64 rows x 64 f4)
            int r  = f4 >> 6;
            int kb = (f4 & 63) << 2;
            float4 v = Ain[f4];
            As[(kb + 0) * TM + r] = v.x;
            As[(kb + 1) * TM + r] = v.y;
            As[(kb + 2) * TM + r] = v.z;
            As[(kb + 3) * TM + r] = v.w;
        }
    }

    // ---- B producer: chunk c -> buffer (c&1), 4096 x 16B granules ----
    auto stageB = [&](uint32_t off, int c) {
        const char* base = (const char*)embed + (size_t)(colBase + c * TN) * 4;
        for (int v = tid; v < 4096; v += 256) {
            int k = v >> 4, g = v & 15;   // 256 k-rows x 16 granules (256B/row)
            cpasync16(sb + off + (uint32_t)k * 256 + g * 16,
                      base + (size_t)k * (NE * 4) + g * 16);
        }
    };
    stageB(OFF_B0, 0);
    CP_COMMIT();

    unsigned int bKey[4];
    int bIdx[4];
    #pragma unroll
    for (int i = 0; i < 4; i++) { bKey[i] = 0xFFFFFFFFu; bIdx[i] = 0; }

    for (int c = 0; c < CH; c++) {
        __syncthreads();                  // buffer (c+1)&1 free (computed at c-1)
        if (c + 1 < CH) {
            stageB((c + 1) & 1 ? OFF_B1 : OFF_B0, c + 1);
            CP_COMMIT();
            CP_WAIT1();                   // chunk c's fill complete
        } else {
            CP_WAIT0();
        }
        __syncthreads();

        const float* Bs = (const float*)((char*)smem + ((c & 1) ? OFF_B1 : OFF_B0));
        const int cb = colBase + c * TN;

        float acc[4][4] = {};
        #pragma unroll 8
        for (int k = 0; k < DIM; k++) {
            float4 av = *(const float4*)(As + k * TM + (ty << 2));
            float4 bv = *(const float4*)(Bs + k * TN + (tx << 2));
            float a_[4] = {av.x, av.y, av.z, av.w};
            float b_[4] = {bv.x, bv.y, bv.z, bv.w};
            #pragma unroll
            for (int i = 0; i < 4; i++)
                #pragma unroll
                for (int jj = 0; jj < 4; jj++)
                    acc[i][jj] = fmaf(a_[i], b_[jj], acc[i][jj]);
        }

        // epilogue: score = ||e||^2 - 2*dot ; argmin with first-index ties
        #pragma unroll
        for (int jj = 0; jj < 4; jj++) {
            int jg = cb + (tx << 2) + jj;
            float nrm = g_norms[jg];
            #pragma unroll
            for (int i = 0; i < 4; i++) {
                float s = fmaf(-2.f, acc[i][jj], nrm);
                unsigned u = __float_as_uint(s);
                unsigned key = (u & 0x80000000u) ? ~u : (u | 0x80000000u);
                if (key < bKey[i]) { bKey[i] = key; bIdx[i] = jg; }
            }
        }
    }

    // ---- combine argmin: smem across threads, then global across halves ----
    #pragma unroll
    for (int i = 0; i < 4; i++) {
        unsigned long long p =
            ((unsigned long long)bKey[i] << 32) | (unsigned)bIdx[i];
        atomicMin(&bestP[(ty << 2) + i], p);
    }
    __syncthreads();
    if (tid < TM)
        atomicMin(&g_best[rowBase + tid], bestP[tid]);
}

// ---------------------------------------------------------------------------
// Finalize indices
// ---------------------------------------------------------------------------
__global__ void vq_fin(float* __restrict__ out) {
    int row = blockIdx.x * 256 + threadIdx.x;
    int j = (int)(g_best[row] & 0xFFFFFFFFull);
    g_idx[row] = j;
    out[INDOFF + row] = (float)j;
}

// ---------------------------------------------------------------------------
// Output: gather + straight-through + per-block loss partial
// ---------------------------------------------------------------------------
__global__ void __launch_bounds__(256) vq_output(const float* __restrict__ input,
                                                 float* __restrict__ out) {
    __shared__ int sIdx[64];
    __shared__ float red[256];
    const int tid = threadIdx.x;
    const int rowBase = blockIdx.x * 64;
    if (tid < 64) sIdx[tid] = g_idx[rowBase + tid];
    __syncthreads();
    float lsum = 0.f;
    for (int r = 0; r < 64; r++) {
        int j = sIdx[r];
        float q = g_embedT[(size_t)j * DIM + tid];
        float x = input[(size_t)(rowBase + r) * DIM + tid];
        float d = q - x;
        out[(size_t)(rowBase + r) * DIM + tid] = x + d;   // straight-through
        lsum += d * d;
    }
    red[tid] = lsum;
    __syncthreads();
    #pragma unroll
    for (int s = 128; s; s >>= 1) {
        if (tid < s) red[tid] += red[tid + s];
        __syncthreads();
    }
    if (tid == 0) g_partial[blockIdx.x] = red[0];
}

__global__ void vq_loss_final(float* __restrict__ out) {
    __shared__ float red[512];
    red[threadIdx.x] = g_partial[threadIdx.x];
    __syncthreads();
    #pragma unroll
    for (int s = 256; s; s >>= 1) {
        if (threadIdx.x < s) red[threadIdx.x] += red[threadIdx.x + s];
        __syncthreads();
    }
    if (threadIdx.x == 0)
        out[LOSSOFF] = red[0] * (1.0f / (float)(N_ROWS * DIM));
}

// ---------------------------------------------------------------------------
extern "C" void kernel_launch(void* const* d_in, const int* in_sizes, int n_in,
                              void* d_out, int out_size) {
    const float* input = (const float*)d_in[0];   // [8,64,64,256]
    const float* embed = (const float*)d_in[1];   // [256,8192]
    float* out = (float*)d_out;

    cudaFuncSetAttribute(vq_main, cudaFuncAttributeMaxDynamicSharedMemorySize,
                         SMEM_BYTES);

    vq_transpose<<<dim3(NE / 32, DIM / 32), dim3(32, 8)>>>(embed);
    vq_norms<<<NE / 8, 256>>>();
    vq_init<<<N_ROWS / 256, 256>>>();
    vq_main<<<dim3(N_ROWS / TM, 2), 256, SMEM_BYTES>>>(input, embed);
    vq_fin<<<N_ROWS / 256, 256>>>(out);
    vq_output<<<N_ROWS / 64, 256>>>(input, out);
    vq_loss_final<<<1, 512>>>(out);
}